// round 7
// baseline (speedup 1.0000x reference)
#include <cuda_runtime.h>
#include <math.h>
#include <stdint.h>

#define B 16
#define T 2048
#define D 512
#define C 512
#define KW 11
#define KHALF 5
#define THRESH 0.9f
#define MAXTOK 128
#define TILE 32   // t-tile per k_logit block

// ---------------- scratch (no allocation allowed) ----------------
__device__ __align__(16) float g_weff[KW * D];
__device__ float g_beff;
__device__ float g_logit[B * T];
__device__ __align__(16) float g_anorm[B * T];  // alpha_norm
__device__ int   g_fire_t[B * MAXTOK];          // fire time of token n
__device__ float g_fak1[B * MAXTOK];            // ak1 at fire n
__device__ float g_fak2[B * MAXTOK];            // ak2 at fire n
__device__ int   g_nf[B];                       // number of fired tokens

// ---- packed f32x2 helpers (sm_103a) ----
__device__ __forceinline__ unsigned long long pack2(float a, float b) {
    unsigned long long r;
    asm("mov.b64 %0, {%1, %2};" : "=l"(r) : "f"(a), "f"(b));
    return r;
}
__device__ __forceinline__ void unpack2(unsigned long long v, float& a, float& b) {
    asm("mov.b64 {%0, %1}, %2;" : "=f"(a), "=f"(b) : "l"(v));
}
#define FMA2(accv, av, bv) \
    asm("fma.rn.f32x2 %0, %1, %2, %0;" : "+l"(accv) : "l"(av), "l"(bv))

// ---------------- kernel 1: fold projection into conv weights ----------------
__global__ void k_weff(const float* __restrict__ conv_w,
                       const float* __restrict__ conv_b,
                       const float* __restrict__ proj_w,
                       const float* __restrict__ proj_b) {
    int wid  = blockIdx.x * (blockDim.x >> 5) + (threadIdx.x >> 5);
    int lane = threadIdx.x & 31;
    if (wid < KW * D) {
        const float* row = conv_w + (size_t)wid * C;
        float s = 0.f;
        #pragma unroll 4
        for (int c = lane; c < C; c += 32) s += row[c] * proj_w[c];
        #pragma unroll
        for (int o = 16; o; o >>= 1) s += __shfl_down_sync(0xffffffffu, s, o);
        if (lane == 0) g_weff[wid] = s;
    } else if (wid == KW * D) {
        float s = 0.f;
        for (int c = lane; c < C; c += 32) s += conv_b[c] * proj_w[c];
        #pragma unroll
        for (int o = 16; o; o >>= 1) s += __shfl_down_sync(0xffffffffu, s, o);
        if (lane == 0) g_beff = s + proj_b[0];
    }
}

// ---------------- kernel 2: direct conv logits, register sliding window ------
// grid (T/TILE, B), 256 threads: thread owns a float2 d-slice; 11 packed
// weights + 32 f32x2 accumulators in registers; each eouts element read once.
__global__ void __launch_bounds__(256, 2)
k_logit(const float* __restrict__ eouts) {
    int b = blockIdx.y;
    int t0 = blockIdx.x * TILE;
    int tid = threadIdx.x;  // 0..255

    unsigned long long w[KW];
    #pragma unroll
    for (int k = 0; k < KW; k++) {
        float2 wv = ((const float2*)(g_weff + k * D))[tid];
        w[k] = pack2(wv.x, wv.y);
    }

    unsigned long long acc[TILE];
    unsigned long long z = pack2(0.f, 0.f);
    #pragma unroll
    for (int i = 0; i < TILE; i++) acc[i] = z;

    const float2* eb = (const float2*)(eouts + (size_t)b * T * D);
    #pragma unroll
    for (int tt = 0; tt < TILE + 2 * KHALF; tt++) {
        int t = t0 + tt - KHALF;
        float2 v = make_float2(0.f, 0.f);
        if (t >= 0 && t < T) v = eb[(size_t)t * (D / 2) + tid];
        unsigned long long vp = pack2(v.x, v.y);
        #pragma unroll
        for (int k = 0; k < KW; k++) {
            int i = tt - k;             // compile-time constant per (tt,k)
            if (i >= 0 && i < TILE) FMA2(acc[i], vp, w[k]);
        }
    }

    // reduce 256 d-slices per output
    __shared__ float s[TILE][257];
    #pragma unroll
    for (int i = 0; i < TILE; i++) {
        float lo, hi;
        unpack2(acc[i], lo, hi);
        s[i][tid] = lo + hi;
    }
    __syncthreads();
    __shared__ float s2[TILE][8];
    {
        int i = tid >> 3, seg = tid & 7;   // 32 outputs x 8 segments of 32
        float sum = 0.f;
        #pragma unroll
        for (int j = 0; j < 32; j++) sum += s[i][seg * 32 + j];
        s2[i][seg] = sum;
    }
    __syncthreads();
    if (tid < TILE) {
        float tot = g_beff;
        #pragma unroll
        for (int j = 0; j < 8; j++) tot += s2[tid][j];
        g_logit[b * T + t0 + tid] = tot;
    }
}

// ---------------- kernel 3: alpha + prefix + ballot fire search --------------
__global__ void k_alpha_scan(float* __restrict__ out_alpha,
                             const int* __restrict__ elens,
                             const int* __restrict__ ylens) {
    int b = blockIdx.x;
    int tid = threadIdx.x;
    int lane = tid & 31, wid = tid >> 5;

    __shared__ float  sA[T];        // alpha_norm
    __shared__ double sS[T];        // inclusive prefix of alpha_norm
    __shared__ double sWarp[32];
    __shared__ int    s_fire_t[MAXTOK];
    __shared__ float  s_ak1[MAXTOK], s_ak2[MAXTOK];
    __shared__ float  s_asum;

    int el = elens[b];
    int yl = ylens[b];

    // --- step 1: sigmoid alphas + block reduce for asum ---
    float a0, a1;
    {
        double local = 0.0;
        #pragma unroll
        for (int rep = 0; rep < 2; rep++) {
            int t = tid + rep * 1024;
            float lg = g_logit[b * T + t];
            float a = 1.f / (1.f + expf(-lg));
            if (rep == 0) a0 = a; else a1 = a;
            local += (double)a;
        }
        #pragma unroll
        for (int o = 16; o; o >>= 1) local += __shfl_down_sync(0xffffffffu, local, o);
        if (lane == 0) sWarp[wid] = local;
        __syncthreads();
        if (wid == 0) {
            double v = sWarp[lane];
            #pragma unroll
            for (int o = 16; o; o >>= 1) v += __shfl_down_sync(0xffffffffu, v, o);
            if (lane == 0) s_asum = (float)v;
        }
        __syncthreads();
    }
    float asum = s_asum;
    float ylf = (float)yl;

    // --- step 2: alpha_norm ---
    {
        int t0 = tid, t1 = tid + 1024;
        float an0 = a0 / asum * ylf;
        float an1 = a1 / asum * ylf;
        sA[t0] = an0; sA[t1] = an1;
        out_alpha[b * T + t0] = a0;  out_alpha[b * T + t1] = a1;
        g_anorm[b * T + t0] = an0;   g_anorm[b * T + t1] = an1;
    }
    __syncthreads();

    // --- step 3: block inclusive prefix scan (double) ---
    {
        float e0 = sA[2 * tid], e1 = sA[2 * tid + 1];
        double my = (double)e0 + (double)e1;
        double v = my;
        #pragma unroll
        for (int o = 1; o < 32; o <<= 1) {
            double n = __shfl_up_sync(0xffffffffu, v, o);
            if (lane >= o) v += n;
        }
        if (lane == 31) sWarp[wid] = v;
        __syncthreads();
        if (wid == 0) {
            double w = sWarp[lane];
            #pragma unroll
            for (int o = 1; o < 32; o <<= 1) {
                double n = __shfl_up_sync(0xffffffffu, w, o);
                if (lane >= o) w += n;
            }
            sWarp[lane] = w;
        }
        __syncthreads();
        double base = (wid ? sWarp[wid - 1] : 0.0) + (v - my);
        sS[2 * tid]     = base + (double)e0;
        sS[2 * tid + 1] = base + (double)e0 + (double)e1;
    }
    __syncthreads();

    // --- step 4: warp 0 finds fires via monotone ballot sweep ---
    if (wid == 0) {
        double Ccorr = 0.0;
        int ntok = 0;
        int pos = 0;
        while (ntok < yl) {
            double th = (double)THRESH - Ccorr;
            int found = -1;
            for (int base = pos; base < el; base += 32) {
                int t = base + lane;
                bool hit = (t < el) && (sS[t] >= th);
                unsigned m = __ballot_sync(0xffffffffu, hit);
                if (m) { found = base + __ffs(m) - 1; break; }
            }
            if (found < 0) break;
            float a = sA[found];
            float acc = (float)(sS[found] + Ccorr);
            float ak1 = 1.f - acc;
            float ak2 = a - ak1;
            if (lane == 0) {
                s_fire_t[ntok] = found;
                s_ak1[ntok] = ak1;
                s_ak2[ntok] = ak2;
            }
            Ccorr += (double)a - 1.0;
            ntok++;
            pos = found + 1;
        }
        __syncwarp();
        if (lane == 0) g_nf[b] = ntok;
        for (int i = lane; i < ntok; i += 32) {
            g_fire_t[b * MAXTOK + i] = s_fire_t[i];
            g_fak1[b * MAXTOK + i] = s_ak1[i];
            g_fak2[b * MAXTOK + i] = s_ak2[i];
        }
    }
}

// ---------------- kernel 4: fused aws rows + fired reductions ----------------
// grid (L+1, B, 2): z=0 -> fired token n=x (x<L); z=1 -> aws row r=x.
__global__ void __launch_bounds__(1024)
k_out(const float* __restrict__ eouts, float* __restrict__ fired,
      float* __restrict__ aws, const int* __restrict__ elens,
      const int* __restrict__ ylens, int L) {
    int b = blockIdx.y;
    int nf = g_nf[b];

    if (blockIdx.z == 1) {
        // ---- aws row r ----
        int r = blockIdx.x;          // 0..L
        int tid = threadIdx.x;
        float4* row = (float4*)(aws + ((size_t)b * (L + 1) + r) * T);
        if (tid >= T / 4) return;
        if (r > nf) {
            row[tid] = make_float4(0.f, 0.f, 0.f, 0.f);
            return;
        }
        int el = elens[b];
        int yl = ylens[b];
        int   fprev = (r > 0) ? g_fire_t[b * MAXTOK + r - 1] : -1;
        float vprev = (r > 0) ? g_fak2[b * MAXTOK + r - 1] : 0.f;
        int   fr   = (r < nf) ? g_fire_t[b * MAXTOK + r] : -2;
        float vak1 = (r < nf) ? g_fak1[b * MAXTOK + r] : 0.f;
        int aEnd = (r < nf) ? fr : ((r < yl) ? el : fprev);

        const float4* an4 = (const float4*)(g_anorm + b * T);
        float4 a4 = an4[tid];
        float av[4] = {a4.x, a4.y, a4.z, a4.w};
        float ov[4];
        int t0 = 4 * tid;
        #pragma unroll
        for (int j = 0; j < 4; j++) {
            int t = t0 + j;
            float v = 0.f;
            if (t > fprev && t < aEnd) v = av[j];
            else if (t == fprev)       v = vprev;
            else if (t == fr)          v = vak1;
            ov[j] = v;
        }
        row[tid] = make_float4(ov[0], ov[1], ov[2], ov[3]);
        return;
    }

    // ---- fired token n (8-phase) ----
    int n = blockIdx.x;
    if (n >= L) return;
    int d  = threadIdx.x & 127;   // float4 slice of D
    int ph = threadIdx.x >> 7;    // 0..7 time phase

    if (n >= nf) {                // zero-fill unused rows
        if (ph == 0)
            ((float4*)(fired + ((size_t)b * L + n) * D))[d] =
                make_float4(0.f, 0.f, 0.f, 0.f);
        return;
    }

    int e = g_fire_t[b * MAXTOK + n];
    float c1 = g_fak1[b * MAXTOK + n];
    int s; float c0;
    if (n == 0) { s = -1; c0 = 0.f; }
    else { s = g_fire_t[b * MAXTOK + n - 1]; c0 = g_fak2[b * MAXTOK + n - 1]; }

    const float* an = g_anorm + b * T;
    const float4* eb = (const float4*)(eouts + (size_t)b * T * D);

    int t0 = (s >= 0) ? s : 0;
    float4 acc = make_float4(0.f, 0.f, 0.f, 0.f);
    #pragma unroll 2
    for (int t = t0 + ph; t <= e; t += 8) {
        float w = (t == e) ? c1 : ((t == s) ? c0 : an[t]);
        float4 v = eb[(size_t)t * 128 + d];
        acc.x += w * v.x; acc.y += w * v.y;
        acc.z += w * v.z; acc.w += w * v.w;
    }

    __shared__ float4 sAcc[1024];
    sAcc[threadIdx.x] = acc;
    __syncthreads();
    if (ph == 0) {
        #pragma unroll
        for (int p = 1; p < 8; p++) {
            float4 a = sAcc[p * 128 + d];
            acc.x += a.x; acc.y += a.y; acc.z += a.z; acc.w += a.w;
        }
        ((float4*)(fired + ((size_t)b * L + n) * D))[d] = acc;
    }
}

// ---------------- launch ------------------------------------------------------
extern "C" void kernel_launch(void* const* d_in, const int* in_sizes, int n_in,
                              void* d_out, int out_size) {
    const float* eouts  = (const float*)d_in[0];
    const float* conv_w = (const float*)d_in[1];
    const float* conv_b = (const float*)d_in[2];
    const float* proj_w = (const float*)d_in[3];
    const float* proj_b = (const float*)d_in[4];
    const int*   elens  = (const int*)d_in[5];
    const int*   ylens  = (const int*)d_in[6];

    // out = concat(fired[B,L,D], alpha[B,T], aws[B,1,L+1,T])
    int L = (out_size - 2 * B * T) / (B * D + B * T);

    float* out   = (float*)d_out;
    float* fired = out;
    float* alpha = out + (size_t)B * L * D;
    float* aws   = alpha + (size_t)B * T;

    k_weff<<<(KW * D + 1 + 7) / 8, 256>>>(conv_w, conv_b, proj_w, proj_b);
    k_logit<<<dim3(T / TILE, B), 256>>>(eouts);
    k_alpha_scan<<<B, 1024>>>(alpha, elens, ylens);
    k_out<<<dim3(L + 1, B, 2), 1024>>>(eouts, fired, aws, elens, ylens, L);
}

// round 8
// speedup vs baseline: 1.0404x; 1.0404x over previous
#include <cuda_runtime.h>
#include <math.h>
#include <stdint.h>

#define B 16
#define T 2048
#define D 512
#define C 512
#define KW 11
#define KHALF 5
#define THRESH 0.9f
#define MAXTOK 128
#define TILE 32              // t-tile per k_logit block
#define NLOAD (TILE + 2*KHALF)   // 42 timestep loads per block
#define GP 7                 // loads per pipeline group
#define NG (NLOAD / GP)      // 6 groups

// ---------------- scratch (no allocation allowed) ----------------
__device__ __align__(16) float g_weff[KW * D];
__device__ float g_beff;
__device__ float g_logit[B * T];
__device__ __align__(16) float g_anorm[B * T];  // alpha_norm
__device__ int   g_fire_t[B * MAXTOK];          // fire time of token n
__device__ float g_fak1[B * MAXTOK];            // ak1 at fire n
__device__ float g_fak2[B * MAXTOK];            // ak2 at fire n
__device__ int   g_nf[B];                       // number of fired tokens

// ---- packed f32x2 helpers (sm_103a) ----
__device__ __forceinline__ unsigned long long pack2(float a, float b) {
    unsigned long long r;
    asm("mov.b64 %0, {%1, %2};" : "=l"(r) : "f"(a), "f"(b));
    return r;
}
__device__ __forceinline__ void unpack2(unsigned long long v, float& a, float& b) {
    asm("mov.b64 {%0, %1}, %2;" : "=f"(a), "=f"(b) : "l"(v));
}
#define FMA2(accv, av, bv) \
    asm("fma.rn.f32x2 %0, %1, %2, %0;" : "+l"(accv) : "l"(av), "l"(bv))

// ---------------- kernel 1: fold projection into conv weights ----------------
__global__ void k_weff(const float* __restrict__ conv_w,
                       const float* __restrict__ conv_b,
                       const float* __restrict__ proj_w,
                       const float* __restrict__ proj_b) {
    int wid  = blockIdx.x * (blockDim.x >> 5) + (threadIdx.x >> 5);
    int lane = threadIdx.x & 31;
    if (wid < KW * D) {
        const float* row = conv_w + (size_t)wid * C;
        float s = 0.f;
        #pragma unroll 4
        for (int c = lane; c < C; c += 32) s += row[c] * proj_w[c];
        #pragma unroll
        for (int o = 16; o; o >>= 1) s += __shfl_down_sync(0xffffffffu, s, o);
        if (lane == 0) g_weff[wid] = s;
    } else if (wid == KW * D) {
        float s = 0.f;
        for (int c = lane; c < C; c += 32) s += conv_b[c] * proj_w[c];
        #pragma unroll
        for (int o = 16; o; o >>= 1) s += __shfl_down_sync(0xffffffffu, s, o);
        if (lane == 0) g_beff = s + proj_b[0];
    }
}

// ---------------- kernel 2: conv logits, double-buffered load pipeline -------
// grid (T/TILE, B), 256 threads: thread owns a float2 d-slice; loads are
// issued in groups of GP, with group g+1 in flight while group g's FMAs run.
__global__ void __launch_bounds__(256, 2)
k_logit(const float* __restrict__ eouts) {
    int b = blockIdx.y;
    int t0 = blockIdx.x * TILE;
    int tid = threadIdx.x;  // 0..255

    unsigned long long w[KW];
    #pragma unroll
    for (int k = 0; k < KW; k++) {
        float2 wv = ((const float2*)(g_weff + k * D))[tid];
        w[k] = pack2(wv.x, wv.y);
    }

    unsigned long long acc[TILE];
    unsigned long long z = pack2(0.f, 0.f);
    #pragma unroll
    for (int i = 0; i < TILE; i++) acc[i] = z;

    const float2* eb = (const float2*)(eouts + (size_t)b * T * D);

    unsigned long long bufA[GP], bufB[GP];

    // prologue: group 0 loads
    #pragma unroll
    for (int j = 0; j < GP; j++) {
        int t = t0 + j - KHALF;
        float2 v = make_float2(0.f, 0.f);
        if (t >= 0 && t < T) v = eb[(size_t)t * (D / 2) + tid];
        bufA[j] = pack2(v.x, v.y);
    }

    #pragma unroll
    for (int g = 0; g < NG; g++) {
        // issue next group's loads before consuming current buffer
        if (g + 1 < NG) {
            #pragma unroll
            for (int j = 0; j < GP; j++) {
                int tt = (g + 1) * GP + j;
                int t = t0 + tt - KHALF;
                float2 v = make_float2(0.f, 0.f);
                if (t >= 0 && t < T) v = eb[(size_t)t * (D / 2) + tid];
                bufB[j] = pack2(v.x, v.y);
            }
        }
        // consume current group
        #pragma unroll
        for (int j = 0; j < GP; j++) {
            int tt = g * GP + j;
            #pragma unroll
            for (int k = 0; k < KW; k++) {
                int i = tt - k;              // compile-time constant
                if (i >= 0 && i < TILE) FMA2(acc[i], bufA[j], w[k]);
            }
        }
        // rotate buffers (register renaming after full unroll)
        #pragma unroll
        for (int j = 0; j < GP; j++) bufA[j] = bufB[j];
    }

    // reduce 256 d-slices per output
    __shared__ float s[TILE][257];
    #pragma unroll
    for (int i = 0; i < TILE; i++) {
        float lo, hi;
        unpack2(acc[i], lo, hi);
        s[i][tid] = lo + hi;
    }
    __syncthreads();
    __shared__ float s2[TILE][8];
    {
        int i = tid >> 3, seg = tid & 7;   // 32 outputs x 8 segments of 32
        float sum = 0.f;
        #pragma unroll
        for (int j = 0; j < 32; j++) sum += s[i][seg * 32 + j];
        s2[i][seg] = sum;
    }
    __syncthreads();
    if (tid < TILE) {
        float tot = g_beff;
        #pragma unroll
        for (int j = 0; j < 8; j++) tot += s2[tid][j];
        g_logit[b * T + t0 + tid] = tot;
    }
}

// ---------------- kernel 3: alpha + prefix + ballot fire search --------------
__global__ void k_alpha_scan(float* __restrict__ out_alpha,
                             const int* __restrict__ elens,
                             const int* __restrict__ ylens) {
    int b = blockIdx.x;
    int tid = threadIdx.x;
    int lane = tid & 31, wid = tid >> 5;

    __shared__ float  sA[T];        // alpha_norm
    __shared__ double sS[T];        // inclusive prefix of alpha_norm
    __shared__ double sWarp[32];
    __shared__ int    s_fire_t[MAXTOK];
    __shared__ float  s_ak1[MAXTOK], s_ak2[MAXTOK];
    __shared__ float  s_asum;

    int el = elens[b];
    int yl = ylens[b];

    // --- step 1: sigmoid alphas + block reduce for asum ---
    float a0, a1;
    {
        double local = 0.0;
        #pragma unroll
        for (int rep = 0; rep < 2; rep++) {
            int t = tid + rep * 1024;
            float lg = g_logit[b * T + t];
            float a = 1.f / (1.f + expf(-lg));
            if (rep == 0) a0 = a; else a1 = a;
            local += (double)a;
        }
        #pragma unroll
        for (int o = 16; o; o >>= 1) local += __shfl_down_sync(0xffffffffu, local, o);
        if (lane == 0) sWarp[wid] = local;
        __syncthreads();
        if (wid == 0) {
            double v = sWarp[lane];
            #pragma unroll
            for (int o = 16; o; o >>= 1) v += __shfl_down_sync(0xffffffffu, v, o);
            if (lane == 0) s_asum = (float)v;
        }
        __syncthreads();
    }
    float asum = s_asum;
    float ylf = (float)yl;

    // --- step 2: alpha_norm ---
    {
        int t0 = tid, t1 = tid + 1024;
        float an0 = a0 / asum * ylf;
        float an1 = a1 / asum * ylf;
        sA[t0] = an0; sA[t1] = an1;
        out_alpha[b * T + t0] = a0;  out_alpha[b * T + t1] = a1;
        g_anorm[b * T + t0] = an0;   g_anorm[b * T + t1] = an1;
    }
    __syncthreads();

    // --- step 3: block inclusive prefix scan (double) ---
    {
        float e0 = sA[2 * tid], e1 = sA[2 * tid + 1];
        double my = (double)e0 + (double)e1;
        double v = my;
        #pragma unroll
        for (int o = 1; o < 32; o <<= 1) {
            double n = __shfl_up_sync(0xffffffffu, v, o);
            if (lane >= o) v += n;
        }
        if (lane == 31) sWarp[wid] = v;
        __syncthreads();
        if (wid == 0) {
            double w = sWarp[lane];
            #pragma unroll
            for (int o = 1; o < 32; o <<= 1) {
                double n = __shfl_up_sync(0xffffffffu, w, o);
                if (lane >= o) w += n;
            }
            sWarp[lane] = w;
        }
        __syncthreads();
        double base = (wid ? sWarp[wid - 1] : 0.0) + (v - my);
        sS[2 * tid]     = base + (double)e0;
        sS[2 * tid + 1] = base + (double)e0 + (double)e1;
    }
    __syncthreads();

    // --- step 4: warp 0 finds fires via monotone ballot sweep ---
    if (wid == 0) {
        double Ccorr = 0.0;
        int ntok = 0;
        int pos = 0;
        while (ntok < yl) {
            double th = (double)THRESH - Ccorr;
            int found = -1;
            for (int base = pos; base < el; base += 32) {
                int t = base + lane;
                bool hit = (t < el) && (sS[t] >= th);
                unsigned m = __ballot_sync(0xffffffffu, hit);
                if (m) { found = base + __ffs(m) - 1; break; }
            }
            if (found < 0) break;
            float a = sA[found];
            float acc = (float)(sS[found] + Ccorr);
            float ak1 = 1.f - acc;
            float ak2 = a - ak1;
            if (lane == 0) {
                s_fire_t[ntok] = found;
                s_ak1[ntok] = ak1;
                s_ak2[ntok] = ak2;
            }
            Ccorr += (double)a - 1.0;
            ntok++;
            pos = found + 1;
        }
        __syncwarp();
        if (lane == 0) g_nf[b] = ntok;
        for (int i = lane; i < ntok; i += 32) {
            g_fire_t[b * MAXTOK + i] = s_fire_t[i];
            g_fak1[b * MAXTOK + i] = s_ak1[i];
            g_fak2[b * MAXTOK + i] = s_ak2[i];
        }
    }
}

// ---------------- kernel 4: fused aws rows + fired reductions ----------------
// grid (L+1, B, 2): z=0 -> fired token n=x (x<L); z=1 -> aws row r=x.
__global__ void __launch_bounds__(1024)
k_out(const float* __restrict__ eouts, float* __restrict__ fired,
      float* __restrict__ aws, const int* __restrict__ elens,
      const int* __restrict__ ylens, int L) {
    int b = blockIdx.y;
    int nf = g_nf[b];

    if (blockIdx.z == 1) {
        // ---- aws row r ----
        int r = blockIdx.x;          // 0..L
        int tid = threadIdx.x;
        float4* row = (float4*)(aws + ((size_t)b * (L + 1) + r) * T);
        if (tid >= T / 4) return;
        if (r > nf) {
            row[tid] = make_float4(0.f, 0.f, 0.f, 0.f);
            return;
        }
        int el = elens[b];
        int yl = ylens[b];
        int   fprev = (r > 0) ? g_fire_t[b * MAXTOK + r - 1] : -1;
        float vprev = (r > 0) ? g_fak2[b * MAXTOK + r - 1] : 0.f;
        int   fr   = (r < nf) ? g_fire_t[b * MAXTOK + r] : -2;
        float vak1 = (r < nf) ? g_fak1[b * MAXTOK + r] : 0.f;
        int aEnd = (r < nf) ? fr : ((r < yl) ? el : fprev);

        const float4* an4 = (const float4*)(g_anorm + b * T);
        float4 a4 = an4[tid];
        float av[4] = {a4.x, a4.y, a4.z, a4.w};
        float ov[4];
        int t0 = 4 * tid;
        #pragma unroll
        for (int j = 0; j < 4; j++) {
            int t = t0 + j;
            float v = 0.f;
            if (t > fprev && t < aEnd) v = av[j];
            else if (t == fprev)       v = vprev;
            else if (t == fr)          v = vak1;
            ov[j] = v;
        }
        row[tid] = make_float4(ov[0], ov[1], ov[2], ov[3]);
        return;
    }

    // ---- fired token n (8-phase) ----
    int n = blockIdx.x;
    if (n >= L) return;
    int d  = threadIdx.x & 127;   // float4 slice of D
    int ph = threadIdx.x >> 7;    // 0..7 time phase

    if (n >= nf) {                // zero-fill unused rows
        if (ph == 0)
            ((float4*)(fired + ((size_t)b * L + n) * D))[d] =
                make_float4(0.f, 0.f, 0.f, 0.f);
        return;
    }

    int e = g_fire_t[b * MAXTOK + n];
    float c1 = g_fak1[b * MAXTOK + n];
    int s; float c0;
    if (n == 0) { s = -1; c0 = 0.f; }
    else { s = g_fire_t[b * MAXTOK + n - 1]; c0 = g_fak2[b * MAXTOK + n - 1]; }

    const float* an = g_anorm + b * T;
    const float4* eb = (const float4*)(eouts + (size_t)b * T * D);

    int t0 = (s >= 0) ? s : 0;
    float4 acc = make_float4(0.f, 0.f, 0.f, 0.f);
    #pragma unroll 2
    for (int t = t0 + ph; t <= e; t += 8) {
        float w = (t == e) ? c1 : ((t == s) ? c0 : an[t]);
        float4 v = eb[(size_t)t * 128 + d];
        acc.x += w * v.x; acc.y += w * v.y;
        acc.z += w * v.z; acc.w += w * v.w;
    }

    __shared__ float4 sAcc[1024];
    sAcc[threadIdx.x] = acc;
    __syncthreads();
    if (ph == 0) {
        #pragma unroll
        for (int p = 1; p < 8; p++) {
            float4 a = sAcc[p * 128 + d];
            acc.x += a.x; acc.y += a.y; acc.z += a.z; acc.w += a.w;
        }
        ((float4*)(fired + ((size_t)b * L + n) * D))[d] = acc;
    }
}

// ---------------- launch ------------------------------------------------------
extern "C" void kernel_launch(void* const* d_in, const int* in_sizes, int n_in,
                              void* d_out, int out_size) {
    const float* eouts  = (const float*)d_in[0];
    const float* conv_w = (const float*)d_in[1];
    const float* conv_b = (const float*)d_in[2];
    const float* proj_w = (const float*)d_in[3];
    const float* proj_b = (const float*)d_in[4];
    const int*   elens  = (const int*)d_in[5];
    const int*   ylens  = (const int*)d_in[6];

    // out = concat(fired[B,L,D], alpha[B,T], aws[B,1,L+1,T])
    int L = (out_size - 2 * B * T) / (B * D + B * T);

    float* out   = (float*)d_out;
    float* fired = out;
    float* alpha = out + (size_t)B * L * D;
    float* aws   = alpha + (size_t)B * T;

    k_weff<<<(KW * D + 1 + 7) / 8, 256>>>(conv_w, conv_b, proj_w, proj_b);
    k_logit<<<dim3(T / TILE, B), 256>>>(eouts);
    k_alpha_scan<<<B, 1024>>>(alpha, elens, ylens);
    k_out<<<dim3(L + 1, B, 2), 1024>>>(eouts, fired, aws, elens, ylens, L);
}

// round 9
// speedup vs baseline: 1.0737x; 1.0321x over previous
#include <cuda_runtime.h>
#include <math.h>
#include <stdint.h>

#define B 16
#define T 2048
#define D 512
#define C 512
#define KW 11
#define KHALF 5
#define THRESH 0.9f
#define MAXTOK 128
#define TILE 16                  // t-tile per k_logit block
#define NLOAD (TILE + 2*KHALF)   // 26 timestep loads per block

// ---------------- scratch (no allocation allowed) ----------------
__device__ __align__(16) float g_weff[KW * D];
__device__ float g_beff;
__device__ float g_logit[B * T];
__device__ __align__(16) float g_anorm[B * T];  // alpha_norm
__device__ int   g_fire_t[B * MAXTOK];          // fire time of token n
__device__ float g_fak1[B * MAXTOK];            // ak1 at fire n
__device__ float g_fak2[B * MAXTOK];            // ak2 at fire n
__device__ int   g_nf[B];                       // number of fired tokens

// ---- packed f32x2 helpers (sm_103a) ----
__device__ __forceinline__ unsigned long long pack2(float a, float b) {
    unsigned long long r;
    asm("mov.b64 %0, {%1, %2};" : "=l"(r) : "f"(a), "f"(b));
    return r;
}
__device__ __forceinline__ void unpack2(unsigned long long v, float& a, float& b) {
    asm("mov.b64 {%0, %1}, %2;" : "=f"(a), "=f"(b) : "l"(v));
}
#define FMA2(accv, av, bv) \
    asm("fma.rn.f32x2 %0, %1, %2, %0;" : "+l"(accv) : "l"(av), "l"(bv))

// ---------------- kernel 1: fold projection into conv weights ----------------
__global__ void k_weff(const float* __restrict__ conv_w,
                       const float* __restrict__ conv_b,
                       const float* __restrict__ proj_w,
                       const float* __restrict__ proj_b) {
    int wid  = blockIdx.x * (blockDim.x >> 5) + (threadIdx.x >> 5);
    int lane = threadIdx.x & 31;
    if (wid < KW * D) {
        const float* row = conv_w + (size_t)wid * C;
        float s = 0.f;
        #pragma unroll 4
        for (int c = lane; c < C; c += 32) s += row[c] * proj_w[c];
        #pragma unroll
        for (int o = 16; o; o >>= 1) s += __shfl_down_sync(0xffffffffu, s, o);
        if (lane == 0) g_weff[wid] = s;
    } else if (wid == KW * D) {
        float s = 0.f;
        for (int c = lane; c < C; c += 32) s += conv_b[c] * proj_w[c];
        #pragma unroll
        for (int o = 16; o; o >>= 1) s += __shfl_down_sync(0xffffffffu, s, o);
        if (lane == 0) g_beff = s + proj_b[0];
    }
}

// ---------------- kernel 2: conv logits, TILE=16, low-register ---------------
// grid (T/TILE, B), 256 threads: thread owns a float2 d-slice; 11 packed
// weights + 16 f32x2 accumulators in registers (~70 regs total -> headroom
// for ptxas to batch the 26 loads); each eouts element read once per block.
__global__ void __launch_bounds__(256, 3)
k_logit(const float* __restrict__ eouts) {
    int b = blockIdx.y;
    int t0 = blockIdx.x * TILE;
    int tid = threadIdx.x;  // 0..255

    unsigned long long w[KW];
    #pragma unroll
    for (int k = 0; k < KW; k++) {
        float2 wv = ((const float2*)(g_weff + k * D))[tid];
        w[k] = pack2(wv.x, wv.y);
    }

    unsigned long long acc[TILE];
    unsigned long long z = pack2(0.f, 0.f);
    #pragma unroll
    for (int i = 0; i < TILE; i++) acc[i] = z;

    const float2* eb = (const float2*)(eouts + (size_t)b * T * D);
    #pragma unroll
    for (int tt = 0; tt < NLOAD; tt++) {
        int t = t0 + tt - KHALF;
        float2 v = make_float2(0.f, 0.f);
        if (t >= 0 && t < T) v = eb[(size_t)t * (D / 2) + tid];
        unsigned long long vp = pack2(v.x, v.y);
        #pragma unroll
        for (int k = 0; k < KW; k++) {
            int i = tt - k;              // compile-time constant per (tt,k)
            if (i >= 0 && i < TILE) FMA2(acc[i], vp, w[k]);
        }
    }

    // reduce 256 d-slices per output (conflict-free mappings)
    __shared__ float s[TILE][257];
    #pragma unroll
    for (int i = 0; i < TILE; i++) {
        float lo, hi;
        unpack2(acc[i], lo, hi);
        s[i][tid] = lo + hi;             // bank = (i + tid) mod 32: CF
    }
    __syncthreads();
    __shared__ float s2[TILE][17];
    {
        int i = tid & 15, seg = tid >> 4;   // 16 outputs x 16 segments of 16
        float sum = 0.f;
        #pragma unroll
        for (int j = 0; j < 16; j++)
            sum += s[i][seg * 16 + j];      // bank = (lane + j) mod 32: CF
        s2[i][seg] = sum;
    }
    __syncthreads();
    if (tid < TILE) {
        float tot = g_beff;
        #pragma unroll
        for (int j = 0; j < 16; j++) tot += s2[tid][j];
        g_logit[b * T + t0 + tid] = tot;
    }
}

// ---------------- kernel 3: alpha + prefix + ballot fire search --------------
__global__ void k_alpha_scan(float* __restrict__ out_alpha,
                             const int* __restrict__ elens,
                             const int* __restrict__ ylens) {
    int b = blockIdx.x;
    int tid = threadIdx.x;
    int lane = tid & 31, wid = tid >> 5;

    __shared__ float  sA[T];        // alpha_norm
    __shared__ double sS[T];        // inclusive prefix of alpha_norm
    __shared__ double sWarp[32];
    __shared__ int    s_fire_t[MAXTOK];
    __shared__ float  s_ak1[MAXTOK], s_ak2[MAXTOK];
    __shared__ float  s_asum;

    int el = elens[b];
    int yl = ylens[b];

    // --- step 1: sigmoid alphas + block reduce for asum ---
    float a0, a1;
    {
        double local = 0.0;
        #pragma unroll
        for (int rep = 0; rep < 2; rep++) {
            int t = tid + rep * 1024;
            float lg = g_logit[b * T + t];
            float a = 1.f / (1.f + expf(-lg));
            if (rep == 0) a0 = a; else a1 = a;
            local += (double)a;
        }
        #pragma unroll
        for (int o = 16; o; o >>= 1) local += __shfl_down_sync(0xffffffffu, local, o);
        if (lane == 0) sWarp[wid] = local;
        __syncthreads();
        if (wid == 0) {
            double v = sWarp[lane];
            #pragma unroll
            for (int o = 16; o; o >>= 1) v += __shfl_down_sync(0xffffffffu, v, o);
            if (lane == 0) s_asum = (float)v;
        }
        __syncthreads();
    }
    float asum = s_asum;
    float ylf = (float)yl;

    // --- step 2: alpha_norm ---
    {
        int t0 = tid, t1 = tid + 1024;
        float an0 = a0 / asum * ylf;
        float an1 = a1 / asum * ylf;
        sA[t0] = an0; sA[t1] = an1;
        out_alpha[b * T + t0] = a0;  out_alpha[b * T + t1] = a1;
        g_anorm[b * T + t0] = an0;   g_anorm[b * T + t1] = an1;
    }
    __syncthreads();

    // --- step 3: block inclusive prefix scan (double) ---
    {
        float e0 = sA[2 * tid], e1 = sA[2 * tid + 1];
        double my = (double)e0 + (double)e1;
        double v = my;
        #pragma unroll
        for (int o = 1; o < 32; o <<= 1) {
            double n = __shfl_up_sync(0xffffffffu, v, o);
            if (lane >= o) v += n;
        }
        if (lane == 31) sWarp[wid] = v;
        __syncthreads();
        if (wid == 0) {
            double w = sWarp[lane];
            #pragma unroll
            for (int o = 1; o < 32; o <<= 1) {
                double n = __shfl_up_sync(0xffffffffu, w, o);
                if (lane >= o) w += n;
            }
            sWarp[lane] = w;
        }
        __syncthreads();
        double base = (wid ? sWarp[wid - 1] : 0.0) + (v - my);
        sS[2 * tid]     = base + (double)e0;
        sS[2 * tid + 1] = base + (double)e0 + (double)e1;
    }
    __syncthreads();

    // --- step 4: warp 0 finds fires via monotone ballot sweep ---
    if (wid == 0) {
        double Ccorr = 0.0;
        int ntok = 0;
        int pos = 0;
        while (ntok < yl) {
            double th = (double)THRESH - Ccorr;
            int found = -1;
            for (int base = pos; base < el; base += 32) {
                int t = base + lane;
                bool hit = (t < el) && (sS[t] >= th);
                unsigned m = __ballot_sync(0xffffffffu, hit);
                if (m) { found = base + __ffs(m) - 1; break; }
            }
            if (found < 0) break;
            float a = sA[found];
            float acc = (float)(sS[found] + Ccorr);
            float ak1 = 1.f - acc;
            float ak2 = a - ak1;
            if (lane == 0) {
                s_fire_t[ntok] = found;
                s_ak1[ntok] = ak1;
                s_ak2[ntok] = ak2;
            }
            Ccorr += (double)a - 1.0;
            ntok++;
            pos = found + 1;
        }
        __syncwarp();
        if (lane == 0) g_nf[b] = ntok;
        for (int i = lane; i < ntok; i += 32) {
            g_fire_t[b * MAXTOK + i] = s_fire_t[i];
            g_fak1[b * MAXTOK + i] = s_ak1[i];
            g_fak2[b * MAXTOK + i] = s_ak2[i];
        }
    }
}

// ---------------- kernel 4: fused aws rows + fired reductions ----------------
// grid (L+1, B, 2): z=0 -> fired token n=x (x<L); z=1 -> aws row r=x.
__global__ void __launch_bounds__(1024)
k_out(const float* __restrict__ eouts, float* __restrict__ fired,
      float* __restrict__ aws, const int* __restrict__ elens,
      const int* __restrict__ ylens, int L) {
    int b = blockIdx.y;
    int nf = g_nf[b];

    if (blockIdx.z == 1) {
        // ---- aws row r ----
        int r = blockIdx.x;          // 0..L
        int tid = threadIdx.x;
        float4* row = (float4*)(aws + ((size_t)b * (L + 1) + r) * T);
        if (tid >= T / 4) return;
        if (r > nf) {
            row[tid] = make_float4(0.f, 0.f, 0.f, 0.f);
            return;
        }
        int el = elens[b];
        int yl = ylens[b];
        int   fprev = (r > 0) ? g_fire_t[b * MAXTOK + r - 1] : -1;
        float vprev = (r > 0) ? g_fak2[b * MAXTOK + r - 1] : 0.f;
        int   fr   = (r < nf) ? g_fire_t[b * MAXTOK + r] : -2;
        float vak1 = (r < nf) ? g_fak1[b * MAXTOK + r] : 0.f;
        int aEnd = (r < nf) ? fr : ((r < yl) ? el : fprev);

        const float4* an4 = (const float4*)(g_anorm + b * T);
        float4 a4 = an4[tid];
        float av[4] = {a4.x, a4.y, a4.z, a4.w};
        float ov[4];
        int t0 = 4 * tid;
        #pragma unroll
        for (int j = 0; j < 4; j++) {
            int t = t0 + j;
            float v = 0.f;
            if (t > fprev && t < aEnd) v = av[j];
            else if (t == fprev)       v = vprev;
            else if (t == fr)          v = vak1;
            ov[j] = v;
        }
        row[tid] = make_float4(ov[0], ov[1], ov[2], ov[3]);
        return;
    }

    // ---- fired token n (8-phase) ----
    int n = blockIdx.x;
    if (n >= L) return;
    int d  = threadIdx.x & 127;   // float4 slice of D
    int ph = threadIdx.x >> 7;    // 0..7 time phase

    if (n >= nf) {                // zero-fill unused rows
        if (ph == 0)
            ((float4*)(fired + ((size_t)b * L + n) * D))[d] =
                make_float4(0.f, 0.f, 0.f, 0.f);
        return;
    }

    int e = g_fire_t[b * MAXTOK + n];
    float c1 = g_fak1[b * MAXTOK + n];
    int s; float c0;
    if (n == 0) { s = -1; c0 = 0.f; }
    else { s = g_fire_t[b * MAXTOK + n - 1]; c0 = g_fak2[b * MAXTOK + n - 1]; }

    const float* an = g_anorm + b * T;
    const float4* eb = (const float4*)(eouts + (size_t)b * T * D);

    int t0 = (s >= 0) ? s : 0;
    float4 acc = make_float4(0.f, 0.f, 0.f, 0.f);
    #pragma unroll 2
    for (int t = t0 + ph; t <= e; t += 8) {
        float w = (t == e) ? c1 : ((t == s) ? c0 : an[t]);
        float4 v = eb[(size_t)t * 128 + d];
        acc.x += w * v.x; acc.y += w * v.y;
        acc.z += w * v.z; acc.w += w * v.w;
    }

    __shared__ float4 sAcc[1024];
    sAcc[threadIdx.x] = acc;
    __syncthreads();
    if (ph == 0) {
        #pragma unroll
        for (int p = 1; p < 8; p++) {
            float4 a = sAcc[p * 128 + d];
            acc.x += a.x; acc.y += a.y; acc.z += a.z; acc.w += a.w;
        }
        ((float4*)(fired + ((size_t)b * L + n) * D))[d] = acc;
    }
}

// ---------------- launch ------------------------------------------------------
extern "C" void kernel_launch(void* const* d_in, const int* in_sizes, int n_in,
                              void* d_out, int out_size) {
    const float* eouts  = (const float*)d_in[0];
    const float* conv_w = (const float*)d_in[1];
    const float* conv_b = (const float*)d_in[2];
    const float* proj_w = (const float*)d_in[3];
    const float* proj_b = (const float*)d_in[4];
    const int*   elens  = (const int*)d_in[5];
    const int*   ylens  = (const int*)d_in[6];

    // out = concat(fired[B,L,D], alpha[B,T], aws[B,1,L+1,T])
    int L = (out_size - 2 * B * T) / (B * D + B * T);

    float* out   = (float*)d_out;
    float* fired = out;
    float* alpha = out + (size_t)B * L * D;
    float* aws   = alpha + (size_t)B * T;

    k_weff<<<(KW * D + 1 + 7) / 8, 256>>>(conv_w, conv_b, proj_w, proj_b);
    k_logit<<<dim3(T / TILE, B), 256>>>(eouts);
    k_alpha_scan<<<B, 1024>>>(alpha, elens, ylens);
    k_out<<<dim3(L + 1, B, 2), 1024>>>(eouts, fired, aws, elens, ylens, L);
}